// round 4
// baseline (speedup 1.0000x reference)
#include <cuda_runtime.h>
#include <cuda_bf16.h>

#define ETA_MIN 0.6931471805599453f
#define ETA_MAX 10.0f

// Elementwise: out[i] = loss[i] > eta ? 0 : 1 - loss[i]/eta
// eta = clamp(eta_value[0], ETA_MIN, ETA_MAX)
// Pure HBM-streaming kernel: 128 MB in + 128 MB out.
__global__ void __launch_bounds__(256)
weights_kernel_vec4(const float4* __restrict__ loss,
                    const float* __restrict__ eta_value,
                    float4* __restrict__ out,
                    int n4) {
    // Scalar eta: single LDG, L2-broadcast across all threads.
    float eta = eta_value[0];
    eta = fminf(fmaxf(eta, ETA_MIN), ETA_MAX);
    const float inv_eta = __frcp_rn(eta);

    int i = blockIdx.x * blockDim.x + threadIdx.x;
    if (i < n4) {
        float4 v = loss[i];
        float4 w;
        w.x = (v.x > eta) ? 0.0f : fmaf(-v.x, inv_eta, 1.0f);
        w.y = (v.y > eta) ? 0.0f : fmaf(-v.y, inv_eta, 1.0f);
        w.z = (v.z > eta) ? 0.0f : fmaf(-v.z, inv_eta, 1.0f);
        w.w = (v.w > eta) ? 0.0f : fmaf(-v.w, inv_eta, 1.0f);
        out[i] = w;
    }
}

// Scalar tail handler for n not divisible by 4 (N=2^25 here, so unused,
// but keep the kernel fully general).
__global__ void weights_kernel_tail(const float* __restrict__ loss,
                                    const float* __restrict__ eta_value,
                                    float* __restrict__ out,
                                    int start, int n) {
    float eta = eta_value[0];
    eta = fminf(fmaxf(eta, ETA_MIN), ETA_MAX);
    const float inv_eta = __frcp_rn(eta);
    int i = start + blockIdx.x * blockDim.x + threadIdx.x;
    if (i < n) {
        float v = loss[i];
        out[i] = (v > eta) ? 0.0f : fmaf(-v, inv_eta, 1.0f);
    }
}

extern "C" void kernel_launch(void* const* d_in, const int* in_sizes, int n_in,
                              void* d_out, int out_size) {
    const float* loss = (const float*)d_in[0];
    const float* eta  = (const float*)d_in[1];
    float* out = (float*)d_out;
    int n = in_sizes[0];

    int n4 = n >> 2;           // full float4 groups
    int tail_start = n4 << 2;  // first scalar-tail element

    if (n4 > 0) {
        int threads = 256;
        int blocks = (n4 + threads - 1) / threads;
        weights_kernel_vec4<<<blocks, threads>>>(
            (const float4*)loss, eta, (float4*)out, n4);
    }
    if (tail_start < n) {
        int rem = n - tail_start;
        weights_kernel_tail<<<(rem + 255) / 256, 256>>>(loss, eta, out,
                                                        tail_start, n);
    }
}

// round 5
// speedup vs baseline: 1.0007x; 1.0007x over previous
#include <cuda_runtime.h>
#include <cuda_bf16.h>

#define ETA_MIN 0.6931471805599453f
#define ETA_MAX 10.0f

// Elementwise: out[i] = loss[i] > eta ? 0 : 1 - loss[i]/eta
// eta = clamp(eta_value[0], ETA_MIN, ETA_MAX)
// Pure HBM-streaming kernel: 128 MB in + 128 MB out.
__global__ void __launch_bounds__(256)
weights_kernel_vec4(const float4* __restrict__ loss,
                    const float* __restrict__ eta_value,
                    float4* __restrict__ out,
                    int n4) {
    // Scalar eta: single LDG, L2-broadcast across all threads.
    float eta = eta_value[0];
    eta = fminf(fmaxf(eta, ETA_MIN), ETA_MAX);
    const float inv_eta = __frcp_rn(eta);

    int i = blockIdx.x * blockDim.x + threadIdx.x;
    if (i < n4) {
        float4 v = loss[i];
        float4 w;
        w.x = (v.x > eta) ? 0.0f : fmaf(-v.x, inv_eta, 1.0f);
        w.y = (v.y > eta) ? 0.0f : fmaf(-v.y, inv_eta, 1.0f);
        w.z = (v.z > eta) ? 0.0f : fmaf(-v.z, inv_eta, 1.0f);
        w.w = (v.w > eta) ? 0.0f : fmaf(-v.w, inv_eta, 1.0f);
        out[i] = w;
    }
}

// Scalar tail handler for n not divisible by 4 (N=2^25 here, so unused,
// but keep the kernel fully general).
__global__ void weights_kernel_tail(const float* __restrict__ loss,
                                    const float* __restrict__ eta_value,
                                    float* __restrict__ out,
                                    int start, int n) {
    float eta = eta_value[0];
    eta = fminf(fmaxf(eta, ETA_MIN), ETA_MAX);
    const float inv_eta = __frcp_rn(eta);
    int i = start + blockIdx.x * blockDim.x + threadIdx.x;
    if (i < n) {
        float v = loss[i];
        out[i] = (v > eta) ? 0.0f : fmaf(-v, inv_eta, 1.0f);
    }
}

extern "C" void kernel_launch(void* const* d_in, const int* in_sizes, int n_in,
                              void* d_out, int out_size) {
    const float* loss = (const float*)d_in[0];
    const float* eta  = (const float*)d_in[1];
    float* out = (float*)d_out;
    int n = in_sizes[0];

    int n4 = n >> 2;           // full float4 groups
    int tail_start = n4 << 2;  // first scalar-tail element

    if (n4 > 0) {
        int threads = 256;
        int blocks = (n4 + threads - 1) / threads;
        weights_kernel_vec4<<<blocks, threads>>>(
            (const float4*)loss, eta, (float4*)out, n4);
    }
    if (tail_start < n) {
        int rem = n - tail_start;
        weights_kernel_tail<<<(rem + 255) / 256, 256>>>(loss, eta, out,
                                                        tail_start, n);
    }
}

// round 6
// speedup vs baseline: 1.0537x; 1.0530x over previous
#include <cuda_runtime.h>
#include <cuda_bf16.h>

#define ETA_MIN 0.6931471805599453f
#define ETA_MAX 10.0f

#define VPT 4        // float4 vectors per thread (64 B/thread each direction)
#define TPB 256      // threads per block

// out[i] = loss[i] > eta ? 0 : 1 - loss[i]/eta,  eta = clamp(eta_value[0], ln2, 10)
// Pure HBM stream: 128 MB in + 128 MB out. Strategy: 4 independent LDG.128
// batched up front (MLP=4/thread) + streaming cache hints (.cs) both ways.
__global__ void __launch_bounds__(TPB)
weights_kernel_vec4x4(const float4* __restrict__ loss,
                      const float* __restrict__ eta_value,
                      float4* __restrict__ out,
                      int n4) {
    float eta = __ldg(eta_value);
    eta = fminf(fmaxf(eta, ETA_MIN), ETA_MAX);
    const float inv_eta = __frcp_rn(eta);

    // Block-contiguous tiling: block b owns [b*TPB*VPT, ...), each thread's
    // VPT vectors strided by TPB within the tile -> fully coalesced.
    int base = blockIdx.x * (TPB * VPT) + threadIdx.x;

    float4 v[VPT];
    bool valid[VPT];
#pragma unroll
    for (int j = 0; j < VPT; j++) {
        int idx = base + j * TPB;
        valid[j] = idx < n4;
        if (valid[j]) v[j] = __ldcs(&loss[idx]);   // streaming load, MLP=4
    }

#pragma unroll
    for (int j = 0; j < VPT; j++) {
        if (valid[j]) {
            float4 w;
            w.x = (v[j].x > eta) ? 0.0f : fmaf(-v[j].x, inv_eta, 1.0f);
            w.y = (v[j].y > eta) ? 0.0f : fmaf(-v[j].y, inv_eta, 1.0f);
            w.z = (v[j].z > eta) ? 0.0f : fmaf(-v[j].z, inv_eta, 1.0f);
            w.w = (v[j].w > eta) ? 0.0f : fmaf(-v[j].w, inv_eta, 1.0f);
            __stcs(&out[base + j * TPB], w);       // streaming store
        }
    }
}

// Scalar tail for n % 4 != 0 (unused for N=2^25; kept for generality).
__global__ void weights_kernel_tail(const float* __restrict__ loss,
                                    const float* __restrict__ eta_value,
                                    float* __restrict__ out,
                                    int start, int n) {
    float eta = __ldg(eta_value);
    eta = fminf(fmaxf(eta, ETA_MIN), ETA_MAX);
    const float inv_eta = __frcp_rn(eta);
    int i = start + blockIdx.x * blockDim.x + threadIdx.x;
    if (i < n) {
        float v = loss[i];
        out[i] = (v > eta) ? 0.0f : fmaf(-v, inv_eta, 1.0f);
    }
}

extern "C" void kernel_launch(void* const* d_in, const int* in_sizes, int n_in,
                              void* d_out, int out_size) {
    const float* loss = (const float*)d_in[0];
    const float* eta  = (const float*)d_in[1];
    float* out = (float*)d_out;
    int n = in_sizes[0];

    int n4 = n >> 2;
    int tail_start = n4 << 2;

    if (n4 > 0) {
        int per_block = TPB * VPT;
        int blocks = (n4 + per_block - 1) / per_block;
        weights_kernel_vec4x4<<<blocks, TPB>>>(
            (const float4*)loss, eta, (float4*)out, n4);
    }
    if (tail_start < n) {
        int rem = n - tail_start;
        weights_kernel_tail<<<(rem + 255) / 256, 256>>>(loss, eta, out,
                                                        tail_start, n);
    }
}